// round 6
// baseline (speedup 1.0000x reference)
#include <cuda_runtime.h>
#include <cstddef>

#define Bc 32
#define Tc 4096
#define Dc 128
#define CHUNKS 16
#define ROWS (Tc / CHUNKS)   // 256 rows per block
#define NEG_FILL (-1e30f)
#define ALPHA 0.5f

// Scratch (fully overwritten every launch -> no init kernel needed, graph-safe)
__device__ float g_part[Bc * CHUNKS * 4 * Dc];  // [b][chunk][stat][d]; stat: 0=maxOutFirst 1=maxLabFirst 2=maxOutSecond 3=maxLabSecond
__device__ float g_sumsq[Bc * CHUNKS];
__device__ float g_bres1[Bc];
__device__ float g_bres2[Bc];

// lengths may arrive as int64 (declared) or int32 (JAX x64 disabled).
// Detect from the first 128 bytes: int32 payload read as int64 yields values
// outside [0, 2^31) unless all odd int32 slots are zero (prob ~ (1/4096)^16).
__device__ __forceinline__ long long read_len(const void* lp, int b) {
    const long long* p64 = (const long long*)lp;
    bool is64 = true;
#pragma unroll
    for (int i = 0; i < 16; i++) {          // 16 * 8B = 128B, safe for both layouts
        long long v = p64[i];
        if (v < 0 || v >= (1LL << 31)) is64 = false;
    }
    if (is64) return p64[b];
    return (long long)((const int*)lp)[b];
}

__device__ __forceinline__ float4 max4(float4 a, float4 b) {
    float4 r;
    r.x = fmaxf(a.x, b.x); r.y = fmaxf(a.y, b.y);
    r.z = fmaxf(a.z, b.z); r.w = fmaxf(a.w, b.w);
    return r;
}

// Streaming (evict-first) float4 load: data is single-use, 128 MB >> L2.
__device__ __forceinline__ float4 ldcs4(const float4* p) {
    float4 v;
    asm volatile("ld.global.cs.v4.f32 {%0,%1,%2,%3}, [%4];"
                 : "=f"(v.x), "=f"(v.y), "=f"(v.z), "=f"(v.w)
                 : "l"(p));
    return v;
}

__global__ __launch_bounds__(256) void seg_k1(
    const float4* __restrict__ O, const float4* __restrict__ Lb,
    const void* __restrict__ lens)
{
    const int b   = blockIdx.y;
    const int c   = blockIdx.x;
    const int tid = threadIdx.x;
    const int col4 = tid & 31;      // d-group (4 floats); D=128 -> 32 float4 per row
    const int rg   = tid >> 5;      // row group 0..7; whole warp shares one t -> uniform branches

    const long long len  = read_len(lens, b);
    const long long half = len >> 1;
    const int t0 = c * ROWS;

    const float4* Op = O  + ((size_t)b * Tc + t0) * 32 + col4;
    const float4* Lp = Lb + ((size_t)b * Tc + t0) * 32 + col4;

    float4 mOF = {NEG_FILL, NEG_FILL, NEG_FILL, NEG_FILL};
    float4 mLF = mOF, mOS = mOF, mLS = mOF;
    float sum = 0.0f;

#pragma unroll 4
    for (int r = rg; r < ROWS; r += 8) {
        float4 o = ldcs4(Op + (size_t)r * 32);
        float4 l = ldcs4(Lp + (size_t)r * 32);
        float dx = o.x - l.x, dy = o.y - l.y, dz = o.z - l.z, dw = o.w - l.w;
        sum += dx * dx + dy * dy + dz * dz + dw * dw;
        long long t = (long long)(t0 + r);
        if (t < half) {                 // warp-uniform
            mOF = max4(mOF, o); mLF = max4(mLF, l);
        } else if (t < len) {
            mOS = max4(mOS, o); mLS = max4(mLS, l);
        }
    }

    __shared__ float4 sm[4 * 8 * 32];   // [stat][rg][col4] = 16 KB
    sm[(0 * 8 + rg) * 32 + col4] = mOF;
    sm[(1 * 8 + rg) * 32 + col4] = mLF;
    sm[(2 * 8 + rg) * 32 + col4] = mOS;
    sm[(3 * 8 + rg) * 32 + col4] = mLS;

    __shared__ float ss[256];
    ss[tid] = sum;
    __syncthreads();

    if (tid < 32) {
#pragma unroll
        for (int stat = 0; stat < 4; stat++) {
            float4 m = sm[(stat * 8 + 0) * 32 + tid];
#pragma unroll
            for (int r = 1; r < 8; r++)
                m = max4(m, sm[(stat * 8 + r) * 32 + tid]);
            ((float4*)g_part)[((b * CHUNKS + c) * 4 + stat) * 32 + tid] = m;
        }
    }

    for (int s = 128; s > 0; s >>= 1) {
        if (tid < s) ss[tid] += ss[tid + s];
        __syncthreads();
    }
    if (tid == 0) g_sumsq[b * CHUNKS + c] = ss[0];
}

__global__ __launch_bounds__(128) void seg_k2(const void* __restrict__ lens)
{
    const int b = blockIdx.x;
    const int d = threadIdx.x;     // 0..127

    float mOF = NEG_FILL, mLF = NEG_FILL, mOS = NEG_FILL, mLS = NEG_FILL;
#pragma unroll
    for (int c = 0; c < CHUNKS; c++) {
        const float* p = g_part + (size_t)((b * CHUNKS + c) * 4) * Dc;
        mOF = fmaxf(mOF, p[0 * Dc + d]);
        mLF = fmaxf(mLF, p[1 * Dc + d]);
        mOS = fmaxf(mOS, p[2 * Dc + d]);
        mLS = fmaxf(mLS, p[3 * Dc + d]);
    }
    float d1 = mOF - mLF;   // empty segment: (-1e30)-(-1e30)=0, matches reference
    float d2 = mOS - mLS;

    __shared__ float s1[128], s2[128];
    s1[d] = d1 * d1;
    s2[d] = d2 * d2;
    __syncthreads();
    for (int s = 64; s > 0; s >>= 1) {
        if (d < s) { s1[d] += s1[d + s]; s2[d] += s2[d + s]; }
        __syncthreads();
    }
    if (d == 0) {
        long long len = read_len(lens, b);
        float valid = (len >= 2) ? 1.0f : 0.0f;
        g_bres1[b] = valid * (s1[0] / (float)Dc);
        g_bres2[b] = valid * (s2[0] / (float)Dc);
    }
}

__global__ void seg_k3(float* __restrict__ out)
{
    const int lane = threadIdx.x;   // 32 threads
    double s = 0.0;                 // fp64: keep final accumulation far from the 1e-3 edge
    for (int i = lane; i < Bc * CHUNKS; i += 32) s += (double)g_sumsq[i];
    float r1 = g_bres1[lane];
    float r2 = g_bres2[lane];
#pragma unroll
    for (int o = 16; o > 0; o >>= 1) {
        s  += __shfl_down_sync(0xFFFFFFFFu, s,  o);
        r1 += __shfl_down_sync(0xFFFFFFFFu, r1, o);
        r2 += __shfl_down_sync(0xFFFFFFFFu, r2, o);
    }
    if (lane == 0) {
        double base = s / (double)((size_t)Bc * Tc * Dc);
        out[0] = (float)(base + (double)ALPHA * (((double)r1 + (double)r2) / (double)Bc));
    }
}

extern "C" void kernel_launch(void* const* d_in, const int* in_sizes, int n_in,
                              void* d_out, int out_size)
{
    const float4* outputs = (const float4*)d_in[0];
    const float4* labels  = (const float4*)d_in[1];
    const void*   lens    = d_in[2];
    float* out = (float*)d_out;

    dim3 g1(CHUNKS, Bc);
    seg_k1<<<g1, 256>>>(outputs, labels, lens);
    seg_k2<<<Bc, 128>>>(lens);
    seg_k3<<<1, 32>>>(out);
}